// round 1
// baseline (speedup 1.0000x reference)
#include <cuda_runtime.h>
#include <math.h>

#define BB   16
#define CC   256
#define NN   2048
#define DQKD 64
#define BINS 32

// ---------------- scratch (device globals; no allocation allowed) ----------------
__device__ float g_q[BB * NN * DQKD];            // [b][n][64]
__device__ float g_k[BB * NN * DQKD];            // [b][m][64]
__device__ float g_v[BB * CC * NN];              // [b][c][n]
__device__ float g_qlt[3 * BB * NN * 64];        // [axis][b][n][64] (63 valid + pad)
__device__ float g_energy[(size_t)BB * NN * NN]; // [b][n][m]  raw energy then attn (in place)
__device__ float g_rowmax[BB * NN];
__device__ float g_rowsuminv[BB * NN];
__device__ float g_colscale[BB * NN];            // colsum then 1/(1e-9+colsum)
__device__ float g_xd[BB * CC * NN];             // x - x_r

// ---------------- K1: channel projection  out = W @ x (+bias) ----------------
// A = W [O x C], B = x[b] [C x N].  Tile 64(o) x 64(n), k-tile 16, 256 thr, 4x4/thr.
template <bool POINT_MAJOR>
__global__ void proj_kernel(const float* __restrict__ W, const float* __restrict__ x,
                            const float* __restrict__ bias, float* __restrict__ out, int O)
{
    __shared__ float As[16 * 65];
    __shared__ float Bs[16 * 64];
    int b  = blockIdx.z;
    int n0 = blockIdx.x * 64;
    int o0 = blockIdx.y * 64;
    int t  = threadIdx.x;
    int ty = t >> 4, tx = t & 15;
    float acc[4][4] = {};
    const float* xb = x + (size_t)b * CC * NN;

    for (int c0 = 0; c0 < CC; c0 += 16) {
#pragma unroll
        for (int i = 0; i < 4; i++) {
            int li = t + i * 256;
            int o = li >> 4, kk = li & 15;
            As[kk * 65 + o] = W[(o0 + o) * CC + c0 + kk];
        }
#pragma unroll
        for (int i = 0; i < 4; i++) {
            int li = t + i * 256;
            int n = li & 63, kk = li >> 6;
            Bs[kk * 64 + n] = xb[(size_t)(c0 + kk) * NN + n0 + n];
        }
        __syncthreads();
#pragma unroll
        for (int kk = 0; kk < 16; kk++) {
            float a[4], bb[4];
#pragma unroll
            for (int i = 0; i < 4; i++) a[i] = As[kk * 65 + ty * 4 + i];
#pragma unroll
            for (int j = 0; j < 4; j++) bb[j] = Bs[kk * 64 + tx * 4 + j];
#pragma unroll
            for (int i = 0; i < 4; i++)
#pragma unroll
                for (int j = 0; j < 4; j++) acc[i][j] += a[i] * bb[j];
        }
        __syncthreads();
    }
#pragma unroll
    for (int i = 0; i < 4; i++) {
        int o = o0 + ty * 4 + i;
        float bval = bias ? bias[o] : 0.f;
#pragma unroll
        for (int j = 0; j < 4; j++) {
            int n = n0 + tx * 4 + j;
            if (POINT_MAJOR)
                out[((size_t)b * NN + n) * O + o] = acc[i][j] + bval;
            else
                out[((size_t)b * O + o) * NN + n] = acc[i][j] + bval;
        }
    }
}

// ---------------- K2: qlt[axis][b][n][r] = sum_j q[b,n,j] * lt[r,j] ----------------
// 256 threads = 4 rows x 64 r-slots (r<63 valid, slot 63 zero-padded).
__global__ void qlt_kernel(const float* __restrict__ q, const float* __restrict__ xlt,
                           const float* __restrict__ ylt, const float* __restrict__ zlt,
                           float* __restrict__ out)
{
    __shared__ float lts[63 * 65];
    __shared__ float qsh[4 * 64];
    int t = threadIdx.x;
    int row0 = blockIdx.x * 4;  // global row over B*N
    qsh[t] = q[(size_t)(row0 + (t >> 6)) * 64 + (t & 63)];
    int r = t & 63, row = t >> 6;
    const float* lt_ptrs[3] = {xlt, ylt, zlt};
    for (int a = 0; a < 3; a++) {
        __syncthreads();
        for (int i = t; i < 63 * 64; i += 256) lts[(i >> 6) * 65 + (i & 63)] = lt_ptrs[a][i];
        __syncthreads();
        float s = 0.f;
        if (r < 63) {
#pragma unroll
            for (int j = 0; j < 64; j++) s += qsh[row * 64 + j] * lts[r * 65 + j];
        }
        out[(size_t)a * BB * NN * 64 + (size_t)(row0 + row) * 64 + r] = s;
    }
}

// ---------------- K3: energy = q k^T + rel-bias, with online row max/sumexp ----------
// Block: 64 query rows x full m sweep. 256 thr (16x16), 4x4 per 64x64 tile.
__global__ void energy_kernel(const float* __restrict__ q, const float* __restrict__ k,
                              const float* __restrict__ qlt, const int* __restrict__ disc,
                              float* __restrict__ energy, float* __restrict__ rowmax,
                              float* __restrict__ rowsuminv)
{
    extern __shared__ float sm[];
    float* qs = sm;                   // 64*64
    float* ks = qs + 64 * 64;         // 64*65
    float* qb = ks + 64 * 65;         // 3*64*64
    int*   dn = (int*)(qb + 3 * 64 * 64); // 64*3
    int*   dm = dn + 192;                 // 64*3

    int b  = blockIdx.y;
    int n0 = blockIdx.x * 64;
    int t  = threadIdx.x;
    int ty = t >> 4, tx = t & 15;

    const size_t qbase = ((size_t)b * NN + n0) * 64;
#pragma unroll
    for (int i = 0; i < 16; i++) qs[t + i * 256] = q[qbase + t + i * 256];
#pragma unroll
    for (int a = 0; a < 3; a++)
#pragma unroll
        for (int i = 0; i < 16; i++)
            qb[a * 4096 + t + i * 256] = qlt[(size_t)a * BB * NN * 64 + qbase + t + i * 256];
    if (t < 192) dn[t] = disc[((size_t)b * NN + n0) * 3 + t];
    __syncthreads();

    int dnr[4][3];
#pragma unroll
    for (int i = 0; i < 4; i++)
#pragma unroll
        for (int a = 0; a < 3; a++) dnr[i][a] = dn[(ty * 4 + i) * 3 + a];

    float rmax[4], rsum[4];
#pragma unroll
    for (int i = 0; i < 4; i++) { rmax[i] = -1e30f; rsum[i] = 0.f; }

    for (int m0 = 0; m0 < NN; m0 += 64) {
        __syncthreads();
#pragma unroll
        for (int i = 0; i < 16; i++) {
            int li = t + i * 256;
            int m = li >> 6, j = li & 63;
            ks[m * 65 + j] = k[((size_t)b * NN + m0 + m) * 64 + j];
        }
        if (t < 192) dm[t] = disc[((size_t)b * NN + m0) * 3 + t];
        __syncthreads();

        float acc[4][4];
#pragma unroll
        for (int i = 0; i < 4; i++)
#pragma unroll
            for (int j = 0; j < 4; j++) acc[i][j] = 0.f;

#pragma unroll
        for (int j = 0; j < 64; j++) {
            float a[4], bb[4];
#pragma unroll
            for (int i = 0; i < 4; i++) a[i] = qs[(ty * 4 + i) * 64 + j];
#pragma unroll
            for (int i = 0; i < 4; i++) bb[i] = ks[(tx * 4 + i) * 65 + j];
#pragma unroll
            for (int i = 0; i < 4; i++)
#pragma unroll
                for (int jj = 0; jj < 4; jj++) acc[i][jj] += a[i] * bb[jj];
        }
        // relative-position bias via smem gathers
#pragma unroll
        for (int jj = 0; jj < 4; jj++) {
            int dmr[3];
#pragma unroll
            for (int a = 0; a < 3; a++) dmr[a] = dm[(tx * 4 + jj) * 3 + a];
#pragma unroll
            for (int i = 0; i < 4; i++) {
                float bias = 0.f;
#pragma unroll
                for (int a = 0; a < 3; a++) {
                    int idx = dmr[a] - dnr[i][a] + (BINS - 1);
                    bias += qb[a * 4096 + (ty * 4 + i) * 64 + idx];
                }
                acc[i][jj] += bias;
            }
        }
        // per-row tile stats, 16-lane butterfly, merge into running stats, store raw tile
#pragma unroll
        for (int i = 0; i < 4; i++) {
            float tm = acc[i][0];
#pragma unroll
            for (int jj = 1; jj < 4; jj++) tm = fmaxf(tm, acc[i][jj]);
            float ts = 0.f;
#pragma unroll
            for (int jj = 0; jj < 4; jj++) ts += __expf(acc[i][jj] - tm);
#pragma unroll
            for (int d = 1; d < 16; d <<= 1) {
                float om = __shfl_xor_sync(0xffffffffu, tm, d);
                float os = __shfl_xor_sync(0xffffffffu, ts, d);
                float nm = fmaxf(tm, om);
                ts = ts * __expf(tm - nm) + os * __expf(om - nm);
                tm = nm;
            }
            float nm = fmaxf(rmax[i], tm);
            rsum[i] = rsum[i] * __expf(rmax[i] - nm) + ts * __expf(tm - nm);
            rmax[i] = nm;

            float4 v4 = make_float4(acc[i][0], acc[i][1], acc[i][2], acc[i][3]);
            *reinterpret_cast<float4*>(
                &energy[((size_t)b * NN + n0 + ty * 4 + i) * NN + m0 + tx * 4]) = v4;
        }
    }
    if (tx == 0) {
#pragma unroll
        for (int i = 0; i < 4; i++) {
            rowmax[b * NN + n0 + ty * 4 + i]    = rmax[i];
            rowsuminv[b * NN + n0 + ty * 4 + i] = 1.f / rsum[i];
        }
    }
}

// ---------------- K4: softmax in place + column sums (for L1 renorm) ----------------
__global__ void zero_kernel(float* p, int n)
{
    int i = blockIdx.x * 256 + threadIdx.x;
    if (i < n) p[i] = 0.f;
}

__global__ void softmax_colsum_kernel(float* __restrict__ energy, const float* __restrict__ rowmax,
                                      const float* __restrict__ rowsuminv, float* __restrict__ colsum)
{
    int b = blockIdx.z;
    int m = blockIdx.x * 128 + threadIdx.x;
    int nstart = blockIdx.y * 256;
    const float* rm = rowmax + b * NN;
    const float* ri = rowsuminv + b * NN;
    float cs = 0.f;
    size_t base = ((size_t)b * NN + nstart) * NN + m;
#pragma unroll 4
    for (int n = 0; n < 256; n++) {
        size_t idx = base + (size_t)n * NN;
        float p = __expf(energy[idx] - rm[nstart + n]) * ri[nstart + n];
        energy[idx] = p;
        cs += p;
    }
    atomicAdd(&colsum[b * NN + m], cs);
}

__global__ void colscale_kernel(float* cs, int n)
{
    int i = blockIdx.x * 256 + threadIdx.x;
    if (i < n) cs[i] = 1.f / (1e-9f + cs[i]);
}

// ---------------- K5: xd = x - (V @ P) * colscale  (128x128 tile, 8x8/thr) ----------
__global__ void xr_kernel(const float* __restrict__ v, const float* __restrict__ attn,
                          const float* __restrict__ colscale, const float* __restrict__ x,
                          float* __restrict__ xd)
{
    __shared__ float As[16 * 132];
    __shared__ float Bs[16 * 128];
    int b  = blockIdx.z;
    int m0 = blockIdx.x * 128;
    int d0 = blockIdx.y * 128;
    int t  = threadIdx.x;
    int ty = t >> 4, tx = t & 15;
    float acc[8][8] = {};
    const float* vb = v + (size_t)b * CC * NN;
    const float* pb = attn + (size_t)b * NN * NN;

    for (int k0 = 0; k0 < NN; k0 += 16) {
#pragma unroll
        for (int i = 0; i < 8; i++) {
            int li = t + i * 256;
            int dd = li >> 4, kk = li & 15;
            As[kk * 132 + dd] = vb[(size_t)(d0 + dd) * NN + k0 + kk];
        }
#pragma unroll
        for (int i = 0; i < 8; i++) {
            int li = t + i * 256;
            int mm = li & 127, kk = li >> 7;
            Bs[kk * 128 + mm] = pb[(size_t)(k0 + kk) * NN + m0 + mm];
        }
        __syncthreads();
#pragma unroll
        for (int kk = 0; kk < 16; kk++) {
            float a[8], bb[8];
#pragma unroll
            for (int i = 0; i < 8; i++) a[i] = As[kk * 132 + ty * 8 + i];
#pragma unroll
            for (int j = 0; j < 8; j++) bb[j] = Bs[kk * 128 + tx * 8 + j];
#pragma unroll
            for (int i = 0; i < 8; i++)
#pragma unroll
                for (int j = 0; j < 8; j++) acc[i][j] += a[i] * bb[j];
        }
        __syncthreads();
    }
    float scale[8];
#pragma unroll
    for (int j = 0; j < 8; j++) scale[j] = colscale[b * NN + m0 + tx * 8 + j];
#pragma unroll
    for (int i = 0; i < 8; i++) {
        size_t idx = ((size_t)b * CC + d0 + ty * 8 + i) * NN + m0 + tx * 8;
#pragma unroll
        for (int j = 0; j < 8; j++) xd[idx + j] = x[idx + j] - acc[i][j] * scale[j];
    }
}

// ---------------- K6: out = x + relu(BN(Wt @ xd + bt)) ------------------------------
__global__ void final_kernel(const float* __restrict__ Wt, const float* __restrict__ xdin,
                             const float* __restrict__ bt, const float* __restrict__ gamma,
                             const float* __restrict__ beta, const float* __restrict__ mean,
                             const float* __restrict__ var, const float* __restrict__ x,
                             float* __restrict__ out)
{
    __shared__ float As[16 * 132];
    __shared__ float Bs[16 * 128];
    int b  = blockIdx.z;
    int m0 = blockIdx.x * 128;
    int o0 = blockIdx.y * 128;
    int t  = threadIdx.x;
    int ty = t >> 4, tx = t & 15;
    float acc[8][8] = {};
    const float* xb = xdin + (size_t)b * CC * NN;

    for (int k0 = 0; k0 < CC; k0 += 16) {
#pragma unroll
        for (int i = 0; i < 8; i++) {
            int li = t + i * 256;
            int oo = li >> 4, kk = li & 15;
            As[kk * 132 + oo] = Wt[(o0 + oo) * CC + k0 + kk];
        }
#pragma unroll
        for (int i = 0; i < 8; i++) {
            int li = t + i * 256;
            int mm = li & 127, kk = li >> 7;
            Bs[kk * 128 + mm] = xb[(size_t)(k0 + kk) * NN + m0 + mm];
        }
        __syncthreads();
#pragma unroll
        for (int kk = 0; kk < 16; kk++) {
            float a[8], bb[8];
#pragma unroll
            for (int i = 0; i < 8; i++) a[i] = As[kk * 132 + ty * 8 + i];
#pragma unroll
            for (int j = 0; j < 8; j++) bb[j] = Bs[kk * 128 + tx * 8 + j];
#pragma unroll
            for (int i = 0; i < 8; i++)
#pragma unroll
                for (int j = 0; j < 8; j++) acc[i][j] += a[i] * bb[j];
        }
        __syncthreads();
    }
#pragma unroll
    for (int i = 0; i < 8; i++) {
        int o = o0 + ty * 8 + i;
        float inv = gamma[o] * rsqrtf(var[o] + 1e-5f);
        float mb = mean[o], bt_ = beta[o], btv = bt[o];
        size_t idx = ((size_t)b * CC + o) * NN + m0 + tx * 8;
#pragma unroll
        for (int j = 0; j < 8; j++) {
            float yv = (acc[i][j] + btv - mb) * inv + bt_;
            out[idx + j] = x[idx + j] + fmaxf(yv, 0.f);
        }
    }
}

// -------------------------------- launcher -----------------------------------------
extern "C" void kernel_launch(void* const* d_in, const int* in_sizes, int n_in,
                              void* d_out, int out_size)
{
    const float* x    = (const float*)d_in[0];
    const int*   disc = (const int*)d_in[1];
    // d_in[2] = xyz (unused by the reference)
    const float* Wq   = (const float*)d_in[3];
    const float* Wk   = (const float*)d_in[4];
    const float* Wv   = (const float*)d_in[5];
    const float* bv   = (const float*)d_in[6];
    const float* xlt  = (const float*)d_in[7];
    const float* ylt  = (const float*)d_in[8];
    const float* zlt  = (const float*)d_in[9];
    const float* Wt   = (const float*)d_in[10];
    const float* bt   = (const float*)d_in[11];
    const float* gamma= (const float*)d_in[12];
    const float* beta = (const float*)d_in[13];
    const float* mean = (const float*)d_in[14];
    const float* var  = (const float*)d_in[15];
    float* out = (float*)d_out;

    float *q, *k, *v, *qlt, *energy, *rowmax, *rowsuminv, *colscale, *xd;
    cudaGetSymbolAddress((void**)&q, g_q);
    cudaGetSymbolAddress((void**)&k, g_k);
    cudaGetSymbolAddress((void**)&v, g_v);
    cudaGetSymbolAddress((void**)&qlt, g_qlt);
    cudaGetSymbolAddress((void**)&energy, g_energy);
    cudaGetSymbolAddress((void**)&rowmax, g_rowmax);
    cudaGetSymbolAddress((void**)&rowsuminv, g_rowsuminv);
    cudaGetSymbolAddress((void**)&colscale, g_colscale);
    cudaGetSymbolAddress((void**)&xd, g_xd);

    const int smem_energy = (64 * 64 + 64 * 65 + 3 * 64 * 64) * 4 + 2 * 192 * 4;
    cudaFuncSetAttribute(energy_kernel, cudaFuncAttributeMaxDynamicSharedMemorySize, smem_energy);

    // K1: projections
    proj_kernel<true><<<dim3(NN / 64, 1, BB), 256>>>(Wq, x, nullptr, q, DQKD);
    proj_kernel<true><<<dim3(NN / 64, 1, BB), 256>>>(Wk, x, nullptr, k, DQKD);
    proj_kernel<false><<<dim3(NN / 64, CC / 64, BB), 256>>>(Wv, x, bv, v, CC);

    // K2: qlt
    qlt_kernel<<<BB * NN / 4, 256>>>(q, xlt, ylt, zlt, qlt);

    // K3: energy + bias + online row stats
    energy_kernel<<<dim3(NN / 64, BB), 256, smem_energy>>>(q, k, qlt, disc, energy, rowmax, rowsuminv);

    // K4: softmax (in place) + column sums -> colscale
    zero_kernel<<<BB * NN / 256, 256>>>(colscale, BB * NN);
    softmax_colsum_kernel<<<dim3(NN / 128, 8, BB), 128>>>(energy, rowmax, rowsuminv, colscale);
    colscale_kernel<<<BB * NN / 256, 256>>>(colscale, BB * NN);

    // K5: xd = x - (V @ P) * colscale
    xr_kernel<<<dim3(NN / 128, CC / 128, BB), 256>>>(v, energy, colscale, x, xd);

    // K6: out = x + relu(BN(Wt @ xd + bt))
    final_kernel<<<dim3(NN / 128, CC / 128, BB), 256>>>(Wt, xd, bt, gamma, beta, mean, var, x, out);
}

// round 2
// speedup vs baseline: 2.2360x; 2.2360x over previous
#include <cuda_runtime.h>
#include <math.h>

#define BB   16
#define CC   256
#define NN   2048
#define DQKD 64
#define BINS 32

// ---------------- scratch (device globals; no allocation allowed) ----------------
__device__ float g_q[BB * NN * DQKD];            // [b][n][64]
__device__ float g_k[BB * NN * DQKD];            // [b][m][64]
__device__ float g_v[BB * CC * NN];              // [b][c][n]
__device__ float g_qlt[3 * BB * NN * 64];        // [axis][b][n][64] (63 valid + pad)
__device__ float g_energy[(size_t)BB * NN * NN]; // [b][n][m]  raw energy then attn (in place)
__device__ float g_rowmax[BB * NN];
__device__ float g_rowsuminv[BB * NN];
__device__ float g_colscale[BB * NN];            // colsum then 1/(1e-9+colsum)
__device__ float g_xd[BB * CC * NN];             // x - x_r

// ---------------- tf32 mma helpers ----------------
__device__ __forceinline__ unsigned f2tf(float f)
{
    unsigned u;
    asm("cvt.rna.tf32.f32 %0, %1;" : "=r"(u) : "f"(f));
    return u;
}

__device__ __forceinline__ void mma_tf32(float c[4], const unsigned a[4], const unsigned b[2])
{
    asm volatile(
        "mma.sync.aligned.m16n8k8.row.col.f32.tf32.tf32.f32 "
        "{%0,%1,%2,%3},{%4,%5,%6,%7},{%8,%9},{%0,%1,%2,%3};"
        : "+f"(c[0]), "+f"(c[1]), "+f"(c[2]), "+f"(c[3])
        : "r"(a[0]), "r"(a[1]), "r"(a[2]), "r"(a[3]), "r"(b[0]), "r"(b[1]));
}

// ---------------- K1: channel projection  out = W @ x (+bias) ----------------
template <bool POINT_MAJOR>
__global__ void proj_kernel(const float* __restrict__ W, const float* __restrict__ x,
                            const float* __restrict__ bias, float* __restrict__ out, int O)
{
    __shared__ float As[16 * 65];
    __shared__ float Bs[16 * 64];
    int b  = blockIdx.z;
    int n0 = blockIdx.x * 64;
    int o0 = blockIdx.y * 64;
    int t  = threadIdx.x;
    int ty = t >> 4, tx = t & 15;
    float acc[4][4] = {};
    const float* xb = x + (size_t)b * CC * NN;

    for (int c0 = 0; c0 < CC; c0 += 16) {
#pragma unroll
        for (int i = 0; i < 4; i++) {
            int li = t + i * 256;
            int o = li >> 4, kk = li & 15;
            As[kk * 65 + o] = W[(o0 + o) * CC + c0 + kk];
        }
#pragma unroll
        for (int i = 0; i < 4; i++) {
            int li = t + i * 256;
            int n = li & 63, kk = li >> 6;
            Bs[kk * 64 + n] = xb[(size_t)(c0 + kk) * NN + n0 + n];
        }
        __syncthreads();
#pragma unroll
        for (int kk = 0; kk < 16; kk++) {
            float a[4], bb[4];
#pragma unroll
            for (int i = 0; i < 4; i++) a[i] = As[kk * 65 + ty * 4 + i];
#pragma unroll
            for (int j = 0; j < 4; j++) bb[j] = Bs[kk * 64 + tx * 4 + j];
#pragma unroll
            for (int i = 0; i < 4; i++)
#pragma unroll
                for (int j = 0; j < 4; j++) acc[i][j] += a[i] * bb[j];
        }
        __syncthreads();
    }
#pragma unroll
    for (int i = 0; i < 4; i++) {
        int o = o0 + ty * 4 + i;
        float bval = bias ? bias[o] : 0.f;
#pragma unroll
        for (int j = 0; j < 4; j++) {
            int n = n0 + tx * 4 + j;
            if (POINT_MAJOR)
                out[((size_t)b * NN + n) * O + o] = acc[i][j] + bval;
            else
                out[((size_t)b * O + o) * NN + n] = acc[i][j] + bval;
        }
    }
}

// ---------------- K2: qlt = q @ lt^T, tiled 64x63x64 per block -----------------------
__global__ void qlt2_kernel(const float* __restrict__ q, const float* __restrict__ xlt,
                            const float* __restrict__ ylt, const float* __restrict__ zlt,
                            float* __restrict__ out)
{
    __shared__ float Qs[64][65];   // [row][k]
    __shared__ float Ls[64][65];   // [k][r] transposed lt
    int a = blockIdx.y;
    const float* lt = (a == 0) ? xlt : ((a == 1) ? ylt : zlt);
    int row0 = blockIdx.x * 64;
    int t = threadIdx.x;

#pragma unroll
    for (int i = 0; i < 4; i++) {
        int idx = t + i * 256;
        int r = idx >> 4, kq = idx & 15;
        float4 f = *reinterpret_cast<const float4*>(&q[(size_t)(row0 + r) * 64 + kq * 4]);
        Qs[r][kq * 4 + 0] = f.x; Qs[r][kq * 4 + 1] = f.y;
        Qs[r][kq * 4 + 2] = f.z; Qs[r][kq * 4 + 3] = f.w;
    }
    if (t < 64) Ls[t][63] = 0.f;
    for (int i = t; i < 63 * 64; i += 256) {
        int r = i >> 6, kk = i & 63;
        Ls[kk][r] = lt[i];
    }
    __syncthreads();

    int ty = t >> 4, tx = t & 15;
    float acc[4][4] = {};
#pragma unroll
    for (int kk = 0; kk < 64; kk++) {
        float av[4], bv2[4];
#pragma unroll
        for (int i = 0; i < 4; i++) av[i] = Qs[ty * 4 + i][kk];
#pragma unroll
        for (int j = 0; j < 4; j++) bv2[j] = Ls[kk][tx * 4 + j];
#pragma unroll
        for (int i = 0; i < 4; i++)
#pragma unroll
            for (int j = 0; j < 4; j++) acc[i][j] += av[i] * bv2[j];
    }
#pragma unroll
    for (int i = 0; i < 4; i++) {
        int row = row0 + ty * 4 + i;
#pragma unroll
        for (int j = 0; j < 4; j++) {
            int r = tx * 4 + j;
            if (r < 63)
                out[(size_t)a * BB * NN * 64 + (size_t)row * 64 + r] = acc[i][j];
        }
    }
}

// ---------------- K3: energy = q k^T + rel-bias (tf32 MMA) + online row stats --------
// Block: 64 query rows, 128 threads (4 warps). m swept in chunks of 128 (32 m / warp).
__global__ void energy_tf32_kernel(const float* __restrict__ q, const float* __restrict__ k,
                                   const float* __restrict__ qlt, const int* __restrict__ disc,
                                   float* __restrict__ energy, float* __restrict__ rowmax,
                                   float* __restrict__ rowsuminv)
{
    extern __shared__ unsigned smu[];
    unsigned* Qs = smu;                       // [64][68] tf32
    unsigned* Ks = Qs + 64 * 68;              // [128][68] tf32
    float* qb = (float*)(Ks + 128 * 68);      // [3][64][64]
    int* dn   = (int*)(qb + 3 * 64 * 64);     // [64*3]
    int* dm   = dn + 192;                     // [128*3]
    float* red = (float*)(dm + 384);          // [4][64][2]

    int b  = blockIdx.y;
    int n0 = blockIdx.x * 64;
    int t  = threadIdx.x;
    int warp = t >> 5, lane = t & 31;

    // load Q (64x64) as tf32
#pragma unroll
    for (int i = 0; i < 8; i++) {
        int idx = t + i * 128;
        int n = idx >> 4, kq = idx & 15;
        float4 f = *reinterpret_cast<const float4*>(&q[((size_t)b * NN + n0 + n) * 64 + kq * 4]);
        Qs[n * 68 + kq * 4 + 0] = f2tf(f.x); Qs[n * 68 + kq * 4 + 1] = f2tf(f.y);
        Qs[n * 68 + kq * 4 + 2] = f2tf(f.z); Qs[n * 68 + kq * 4 + 3] = f2tf(f.w);
    }
    // load qlt gather tables (3 x 64 x 64)
#pragma unroll
    for (int i = 0; i < 24; i++) {
        int idx = t + i * 128;                 // float4 index into 3072
        int a = idx >> 10, rem = idx & 1023;
        int n = rem >> 4, kq = rem & 15;
        float4 f = *reinterpret_cast<const float4*>(
            &qlt[(size_t)a * BB * NN * 64 + ((size_t)b * NN + n0 + n) * 64 + kq * 4]);
        float* dst = &qb[a * 4096 + n * 64 + kq * 4];
        dst[0] = f.x; dst[1] = f.y; dst[2] = f.z; dst[3] = f.w;
    }
    if (t < 192) dn[t] = disc[((size_t)b * NN + n0) * 3 + t];
    if (t + 128 < 192) dn[t + 128] = disc[((size_t)b * NN + n0) * 3 + t + 128];
    __syncthreads();

    int dn_r[4][2][3];
#pragma unroll
    for (int mt = 0; mt < 4; mt++)
#pragma unroll
        for (int h = 0; h < 2; h++) {
            int row_l = mt * 16 + h * 8 + (lane >> 2);
#pragma unroll
            for (int a = 0; a < 3; a++) dn_r[mt][h][a] = dn[row_l * 3 + a];
        }

    float rmx[4][2], rsm[4][2];
#pragma unroll
    for (int mt = 0; mt < 4; mt++)
#pragma unroll
        for (int h = 0; h < 2; h++) { rmx[mt][h] = -1e30f; rsm[mt][h] = 0.f; }

    for (int m0c = 0; m0c < NN; m0c += 128) {
        __syncthreads();
        // load K chunk (128 x 64) tf32
#pragma unroll
        for (int i = 0; i < 16; i++) {
            int idx = t + i * 128;
            int m = idx >> 4, kq = idx & 15;
            float4 f = *reinterpret_cast<const float4*>(
                &k[((size_t)b * NN + m0c + m) * 64 + kq * 4]);
            Ks[m * 68 + kq * 4 + 0] = f2tf(f.x); Ks[m * 68 + kq * 4 + 1] = f2tf(f.y);
            Ks[m * 68 + kq * 4 + 2] = f2tf(f.z); Ks[m * 68 + kq * 4 + 3] = f2tf(f.w);
        }
#pragma unroll
        for (int i = 0; i < 3; i++)
            dm[t + i * 128] = disc[((size_t)b * NN + m0c) * 3 + t + i * 128];
        __syncthreads();

        float c[4][4][4] = {};
#pragma unroll
        for (int ks = 0; ks < 8; ks++) {
            unsigned af[4][4], bf[4][2];
#pragma unroll
            for (int mt = 0; mt < 4; mt++) {
                int row = mt * 16 + (lane >> 2);
                int col = ks * 8 + (lane & 3);
                af[mt][0] = Qs[row * 68 + col];
                af[mt][1] = Qs[(row + 8) * 68 + col];
                af[mt][2] = Qs[row * 68 + col + 4];
                af[mt][3] = Qs[(row + 8) * 68 + col + 4];
            }
#pragma unroll
            for (int nt = 0; nt < 4; nt++) {
                int cm = warp * 32 + nt * 8 + (lane >> 2);
                int kk = ks * 8 + (lane & 3);
                bf[nt][0] = Ks[cm * 68 + kk];
                bf[nt][1] = Ks[cm * 68 + kk + 4];
            }
#pragma unroll
            for (int mt = 0; mt < 4; mt++)
#pragma unroll
                for (int nt = 0; nt < 4; nt++) mma_tf32(c[mt][nt], af[mt], bf[nt]);
        }

        // bias + stats + store
#pragma unroll
        for (int mt = 0; mt < 4; mt++)
#pragma unroll
            for (int h = 0; h < 2; h++) {
                int row_l = mt * 16 + h * 8 + (lane >> 2);
                float ev[4][2];
#pragma unroll
                for (int nt = 0; nt < 4; nt++) {
                    int col0 = warp * 32 + nt * 8 + (lane & 3) * 2;
#pragma unroll
                    for (int j = 0; j < 2; j++) {
                        int col = col0 + j;
                        float e = c[mt][nt][h * 2 + j];
#pragma unroll
                        for (int a = 0; a < 3; a++) {
                            int idx = dm[col * 3 + a] - dn_r[mt][h][a] + (BINS - 1);
                            e += qb[a * 4096 + row_l * 64 + idx];
                        }
                        ev[nt][j] = e;
                    }
                }
                float tm = ev[0][0];
#pragma unroll
                for (int nt = 0; nt < 4; nt++)
#pragma unroll
                    for (int j = 0; j < 2; j++) tm = fmaxf(tm, ev[nt][j]);
                float ts = 0.f;
#pragma unroll
                for (int nt = 0; nt < 4; nt++)
#pragma unroll
                    for (int j = 0; j < 2; j++) ts += __expf(ev[nt][j] - tm);
                float nm = fmaxf(rmx[mt][h], tm);
                rsm[mt][h] = rsm[mt][h] * __expf(rmx[mt][h] - nm) + ts * __expf(tm - nm);
                rmx[mt][h] = nm;
#pragma unroll
                for (int nt = 0; nt < 4; nt++) {
                    int col0 = warp * 32 + nt * 8 + (lane & 3) * 2;
                    float2 st = make_float2(ev[nt][0], ev[nt][1]);
                    *reinterpret_cast<float2*>(
                        &energy[((size_t)b * NN + n0 + row_l) * NN + m0c + col0]) = st;
                }
            }
    }

    // quad reduce + cross-warp merge
#pragma unroll
    for (int mt = 0; mt < 4; mt++)
#pragma unroll
        for (int h = 0; h < 2; h++) {
            float tm = rmx[mt][h], ts = rsm[mt][h];
#pragma unroll
            for (int d = 1; d < 4; d <<= 1) {
                float om = __shfl_xor_sync(0xffffffffu, tm, d);
                float os = __shfl_xor_sync(0xffffffffu, ts, d);
                float nm = fmaxf(tm, om);
                ts = ts * __expf(tm - nm) + os * __expf(om - nm);
                tm = nm;
            }
            if ((lane & 3) == 0) {
                int row_l = mt * 16 + h * 8 + (lane >> 2);
                red[(warp * 64 + row_l) * 2 + 0] = tm;
                red[(warp * 64 + row_l) * 2 + 1] = ts;
            }
        }
    __syncthreads();
    if (t < 64) {
        float m = -1e30f, s = 0.f;
#pragma unroll
        for (int w = 0; w < 4; w++) {
            float mw = red[(w * 64 + t) * 2 + 0];
            float sw = red[(w * 64 + t) * 2 + 1];
            float nm = fmaxf(m, mw);
            s = s * __expf(m - nm) + sw * __expf(mw - nm);
            m = nm;
        }
        rowmax[b * NN + n0 + t]    = m;
        rowsuminv[b * NN + n0 + t] = 1.f / s;
    }
}

// ---------------- K4: softmax in place + column sums (for L1 renorm) ----------------
__global__ void zero_kernel(float* p, int n)
{
    int i = blockIdx.x * 256 + threadIdx.x;
    if (i < n) p[i] = 0.f;
}

__global__ void softmax_colsum_kernel(float* __restrict__ energy, const float* __restrict__ rowmax,
                                      const float* __restrict__ rowsuminv, float* __restrict__ colsum)
{
    int b = blockIdx.z;
    int m = blockIdx.x * 128 + threadIdx.x;
    int nstart = blockIdx.y * 256;
    const float* rm = rowmax + b * NN;
    const float* ri = rowsuminv + b * NN;
    float cs = 0.f;
    size_t base = ((size_t)b * NN + nstart) * NN + m;
#pragma unroll 4
    for (int n = 0; n < 256; n++) {
        size_t idx = base + (size_t)n * NN;
        float p = __expf(energy[idx] - rm[nstart + n]) * ri[nstart + n];
        energy[idx] = p;
        cs += p;
    }
    atomicAdd(&colsum[b * NN + m], cs);
}

__global__ void colscale_kernel(float* cs, int n)
{
    int i = blockIdx.x * 256 + threadIdx.x;
    if (i < n) cs[i] = 1.f / (1e-9f + cs[i]);
}

// ---------------- K5: xd = x - (V @ P) * colscale  (tf32 MMA, 128x128 tile) ---------
__global__ void xr_tf32_kernel(const float* __restrict__ v, const float* __restrict__ attn,
                               const float* __restrict__ colscale, const float* __restrict__ x,
                               float* __restrict__ xd)
{
    __shared__ unsigned As[128][36];  // [d][k]
    __shared__ unsigned Bs[32][136];  // [k][m]
    int b  = blockIdx.z;
    int m0 = blockIdx.x * 128;
    int d0 = blockIdx.y * 128;
    int t  = threadIdx.x;
    int warp = t >> 5, lane = t & 31;
    int wm = warp >> 2, wn = warp & 3;
    float c[4][4][4] = {};
    const float* vb = v + (size_t)b * CC * NN;
    const float* pb = attn + (size_t)b * NN * NN;

    for (int k0 = 0; k0 < NN; k0 += 32) {
#pragma unroll
        for (int i = 0; i < 4; i++) {
            int idx = t + i * 256;
            int dd = idx >> 3, kq = idx & 7;
            float4 f = *reinterpret_cast<const float4*>(&vb[(size_t)(d0 + dd) * NN + k0 + kq * 4]);
            As[dd][kq * 4 + 0] = f2tf(f.x); As[dd][kq * 4 + 1] = f2tf(f.y);
            As[dd][kq * 4 + 2] = f2tf(f.z); As[dd][kq * 4 + 3] = f2tf(f.w);
        }
#pragma unroll
        for (int i = 0; i < 4; i++) {
            int idx = t + i * 256;
            int kk = idx >> 5, mq = idx & 31;
            float4 f = *reinterpret_cast<const float4*>(&pb[(size_t)(k0 + kk) * NN + m0 + mq * 4]);
            Bs[kk][mq * 4 + 0] = f2tf(f.x); Bs[kk][mq * 4 + 1] = f2tf(f.y);
            Bs[kk][mq * 4 + 2] = f2tf(f.z); Bs[kk][mq * 4 + 3] = f2tf(f.w);
        }
        __syncthreads();
#pragma unroll
        for (int ks = 0; ks < 4; ks++) {
            unsigned af[4][4], bf[4][2];
#pragma unroll
            for (int mt = 0; mt < 4; mt++) {
                int row = wm * 64 + mt * 16 + (lane >> 2);
                int col = ks * 8 + (lane & 3);
                af[mt][0] = As[row][col];
                af[mt][1] = As[row + 8][col];
                af[mt][2] = As[row][col + 4];
                af[mt][3] = As[row + 8][col + 4];
            }
#pragma unroll
            for (int nt = 0; nt < 4; nt++) {
                int kk = ks * 8 + (lane & 3);
                int cm = wn * 32 + nt * 8 + (lane >> 2);
                bf[nt][0] = Bs[kk][cm];
                bf[nt][1] = Bs[kk + 4][cm];
            }
#pragma unroll
            for (int mt = 0; mt < 4; mt++)
#pragma unroll
                for (int nt = 0; nt < 4; nt++) mma_tf32(c[mt][nt], af[mt], bf[nt]);
        }
        __syncthreads();
    }
#pragma unroll
    for (int mt = 0; mt < 4; mt++)
#pragma unroll
        for (int h = 0; h < 2; h++) {
            int dd = d0 + wm * 64 + mt * 16 + h * 8 + (lane >> 2);
#pragma unroll
            for (int nt = 0; nt < 4; nt++) {
                int mm = m0 + wn * 32 + nt * 8 + (lane & 3) * 2;
                float s0 = colscale[b * NN + mm];
                float s1 = colscale[b * NN + mm + 1];
                size_t idx = ((size_t)b * CC + dd) * NN + mm;
                float2 xv = *reinterpret_cast<const float2*>(&x[idx]);
                float2 o;
                o.x = xv.x - c[mt][nt][h * 2 + 0] * s0;
                o.y = xv.y - c[mt][nt][h * 2 + 1] * s1;
                *reinterpret_cast<float2*>(&xd[idx]) = o;
            }
        }
}

// ---------------- K6: out = x + relu(BN(Wt @ xd + bt)) ------------------------------
__global__ void final_kernel(const float* __restrict__ Wt, const float* __restrict__ xdin,
                             const float* __restrict__ bt, const float* __restrict__ gamma,
                             const float* __restrict__ beta, const float* __restrict__ mean,
                             const float* __restrict__ var, const float* __restrict__ x,
                             float* __restrict__ out)
{
    __shared__ float As[16 * 132];
    __shared__ float Bs[16 * 128];
    int b  = blockIdx.z;
    int m0 = blockIdx.x * 128;
    int o0 = blockIdx.y * 128;
    int t  = threadIdx.x;
    int ty = t >> 4, tx = t & 15;
    float acc[8][8] = {};
    const float* xb = xdin + (size_t)b * CC * NN;

    for (int k0 = 0; k0 < CC; k0 += 16) {
#pragma unroll
        for (int i = 0; i < 8; i++) {
            int li = t + i * 256;
            int oo = li >> 4, kk = li & 15;
            As[kk * 132 + oo] = Wt[(o0 + oo) * CC + k0 + kk];
        }
#pragma unroll
        for (int i = 0; i < 8; i++) {
            int li = t + i * 256;
            int mm = li & 127, kk = li >> 7;
            Bs[kk * 128 + mm] = xb[(size_t)(k0 + kk) * NN + m0 + mm];
        }
        __syncthreads();
#pragma unroll
        for (int kk = 0; kk < 16; kk++) {
            float a[8], bb[8];
#pragma unroll
            for (int i = 0; i < 8; i++) a[i] = As[kk * 132 + ty * 8 + i];
#pragma unroll
            for (int j = 0; j < 8; j++) bb[j] = Bs[kk * 128 + tx * 8 + j];
#pragma unroll
            for (int i = 0; i < 8; i++)
#pragma unroll
                for (int j = 0; j < 8; j++) acc[i][j] += a[i] * bb[j];
        }
        __syncthreads();
    }
#pragma unroll
    for (int i = 0; i < 8; i++) {
        int o = o0 + ty * 8 + i;
        float inv = gamma[o] * rsqrtf(var[o] + 1e-5f);
        float mb = mean[o], bt_ = beta[o], btv = bt[o];
        size_t idx = ((size_t)b * CC + o) * NN + m0 + tx * 8;
#pragma unroll
        for (int j = 0; j < 8; j++) {
            float yv = (acc[i][j] + btv - mb) * inv + bt_;
            out[idx + j] = x[idx + j] + fmaxf(yv, 0.f);
        }
    }
}

// -------------------------------- launcher -----------------------------------------
extern "C" void kernel_launch(void* const* d_in, const int* in_sizes, int n_in,
                              void* d_out, int out_size)
{
    const float* x    = (const float*)d_in[0];
    const int*   disc = (const int*)d_in[1];
    // d_in[2] = xyz (unused by the reference)
    const float* Wq   = (const float*)d_in[3];
    const float* Wk   = (const float*)d_in[4];
    const float* Wv   = (const float*)d_in[5];
    const float* bv   = (const float*)d_in[6];
    const float* xlt  = (const float*)d_in[7];
    const float* ylt  = (const float*)d_in[8];
    const float* zlt  = (const float*)d_in[9];
    const float* Wt   = (const float*)d_in[10];
    const float* bt   = (const float*)d_in[11];
    const float* gamma= (const float*)d_in[12];
    const float* beta = (const float*)d_in[13];
    const float* mean = (const float*)d_in[14];
    const float* var  = (const float*)d_in[15];
    float* out = (float*)d_out;

    float *q, *k, *v, *qlt, *energy, *rowmax, *rowsuminv, *colscale, *xd;
    cudaGetSymbolAddress((void**)&q, g_q);
    cudaGetSymbolAddress((void**)&k, g_k);
    cudaGetSymbolAddress((void**)&v, g_v);
    cudaGetSymbolAddress((void**)&qlt, g_qlt);
    cudaGetSymbolAddress((void**)&energy, g_energy);
    cudaGetSymbolAddress((void**)&rowmax, g_rowmax);
    cudaGetSymbolAddress((void**)&rowsuminv, g_rowsuminv);
    cudaGetSymbolAddress((void**)&colscale, g_colscale);
    cudaGetSymbolAddress((void**)&xd, g_xd);

    // dynamic smem for energy_tf32: Qs + Ks + qb + dn + dm + red
    const int smem_energy = (64 * 68 + 128 * 68) * 4 + 3 * 64 * 64 * 4
                          + 192 * 4 + 384 * 4 + 4 * 64 * 2 * 4;
    cudaFuncSetAttribute(energy_tf32_kernel, cudaFuncAttributeMaxDynamicSharedMemorySize, smem_energy);

    // K1: projections
    proj_kernel<true><<<dim3(NN / 64, 1, BB), 256>>>(Wq, x, nullptr, q, DQKD);
    proj_kernel<true><<<dim3(NN / 64, 1, BB), 256>>>(Wk, x, nullptr, k, DQKD);
    proj_kernel<false><<<dim3(NN / 64, CC / 64, BB), 256>>>(Wv, x, bv, v, CC);

    // K2: qlt (one block per 64 rows per axis)
    qlt2_kernel<<<dim3(BB * NN / 64, 3), 256>>>(q, xlt, ylt, zlt, qlt);

    // K3: energy + bias + online row stats (tf32 MMA)
    energy_tf32_kernel<<<dim3(NN / 64, BB), 128, smem_energy>>>(q, k, qlt, disc, energy,
                                                                rowmax, rowsuminv);

    // K4: softmax (in place) + column sums -> colscale
    zero_kernel<<<BB * NN / 256, 256>>>(colscale, BB * NN);
    softmax_colsum_kernel<<<dim3(NN / 128, 8, BB), 128>>>(energy, rowmax, rowsuminv, colscale);
    colscale_kernel<<<BB * NN / 256, 256>>>(colscale, BB * NN);

    // K5: xd = x - (V @ P) * colscale (tf32 MMA)
    xr_tf32_kernel<<<dim3(NN / 128, CC / 128, BB), 256>>>(v, energy, colscale, x, xd);

    // K6: out = x + relu(BN(Wt @ xd + bt))
    final_kernel<<<dim3(NN / 128, CC / 128, BB), 256>>>(Wt, xd, bt, gamma, beta, mean, var, x, out);
}

// round 3
// speedup vs baseline: 2.4193x; 1.0820x over previous
#include <cuda_runtime.h>
#include <math.h>

#define BB   16
#define CC   256
#define NN   2048
#define DQKD 64
#define BINS 32

// ---------------- scratch (device globals; no allocation allowed) ----------------
__device__ float g_q[BB * NN * DQKD];            // [b][n][64]
__device__ float g_k[BB * NN * DQKD];            // [b][m][64]
__device__ float g_v[BB * CC * NN];              // [b][c][n]
__device__ float g_energy[(size_t)BB * NN * NN]; // [b][n][m]  raw energy
__device__ float g_rowmax[BB * NN];
__device__ float g_rowsuminv[BB * NN];
__device__ float g_xd[BB * CC * NN];             // x - x_r

// ---------------- tf32 mma helpers ----------------
__device__ __forceinline__ unsigned f2tf(float f)
{
    unsigned u;
    asm("cvt.rna.tf32.f32 %0, %1;" : "=r"(u) : "f"(f));
    return u;
}

__device__ __forceinline__ void mma_tf32(float c[4], const unsigned a[4], const unsigned b[2])
{
    asm volatile(
        "mma.sync.aligned.m16n8k8.row.col.f32.tf32.tf32.f32 "
        "{%0,%1,%2,%3},{%4,%5,%6,%7},{%8,%9},{%0,%1,%2,%3};"
        : "+f"(c[0]), "+f"(c[1]), "+f"(c[2]), "+f"(c[3])
        : "r"(a[0]), "r"(a[1]), "r"(a[2]), "r"(a[3]), "r"(b[0]), "r"(b[1]));
}

// ---------------- K1: channel projection  out = W @ x (+bias) ----------------
template <bool POINT_MAJOR>
__global__ void proj_kernel(const float* __restrict__ W, const float* __restrict__ x,
                            const float* __restrict__ bias, float* __restrict__ out, int O)
{
    __shared__ float As[16 * 65];
    __shared__ float Bs[16 * 64];
    int b  = blockIdx.z;
    int n0 = blockIdx.x * 64;
    int o0 = blockIdx.y * 64;
    int t  = threadIdx.x;
    int ty = t >> 4, tx = t & 15;
    float acc[4][4] = {};
    const float* xb = x + (size_t)b * CC * NN;

    for (int c0 = 0; c0 < CC; c0 += 16) {
#pragma unroll
        for (int i = 0; i < 4; i++) {
            int li = t + i * 256;
            int o = li >> 4, kk = li & 15;
            As[kk * 65 + o] = W[(o0 + o) * CC + c0 + kk];
        }
#pragma unroll
        for (int i = 0; i < 4; i++) {
            int li = t + i * 256;
            int n = li & 63, kk = li >> 6;
            Bs[kk * 64 + n] = xb[(size_t)(c0 + kk) * NN + n0 + n];
        }
        __syncthreads();
#pragma unroll
        for (int kk = 0; kk < 16; kk++) {
            float a[4], bb[4];
#pragma unroll
            for (int i = 0; i < 4; i++) a[i] = As[kk * 65 + ty * 4 + i];
#pragma unroll
            for (int j = 0; j < 4; j++) bb[j] = Bs[kk * 64 + tx * 4 + j];
#pragma unroll
            for (int i = 0; i < 4; i++)
#pragma unroll
                for (int j = 0; j < 4; j++) acc[i][j] += a[i] * bb[j];
        }
        __syncthreads();
    }
#pragma unroll
    for (int i = 0; i < 4; i++) {
        int o = o0 + ty * 4 + i;
        float bval = bias ? bias[o] : 0.f;
#pragma unroll
        for (int j = 0; j < 4; j++) {
            int n = n0 + tx * 4 + j;
            if (POINT_MAJOR)
                out[((size_t)b * NN + n) * O + o] = acc[i][j] + bval;
            else
                out[((size_t)b * O + o) * NN + n] = acc[i][j] + bval;
        }
    }
}

// ---------------- K3: energy = q k^T + rel-bias (tf32 MMA, qlt computed in-block) ---
// 256 threads (8 warps). 64 query rows/block. m swept in chunks of 128.
// Warp grid: wr = warp>>2 (row half of 32), wc = warp&3 (col quarter of 32).
__global__ void energy_tf32_kernel(const float* __restrict__ q, const float* __restrict__ k,
                                   const float* __restrict__ xlt, const float* __restrict__ ylt,
                                   const float* __restrict__ zlt, const int* __restrict__ disc,
                                   float* __restrict__ energy, float* __restrict__ rowmax,
                                   float* __restrict__ rowsuminv)
{
    extern __shared__ unsigned smu[];
    unsigned* Qs = smu;                       // [64][68] tf32
    unsigned* Ks = Qs + 64 * 68;              // [128][68] tf32 (also lt staging)
    float* qb = (float*)(Ks + 128 * 68);      // [3][64][64]
    int* dn   = (int*)(qb + 3 * 64 * 64);     // [64*3]
    int* dm   = dn + 192;                     // [128*3]
    float* red = (float*)(dm + 384);          // [4 wc][64][2]

    int b  = blockIdx.y;
    int n0 = blockIdx.x * 64;
    int t  = threadIdx.x;
    int warp = t >> 5, lane = t & 31;
    int wr = warp >> 2, wc = warp & 3;

    // load Q (64x64) as tf32
#pragma unroll
    for (int i = 0; i < 4; i++) {
        int idx = t + i * 256;
        int n = idx >> 4, kq = idx & 15;
        float4 f = *reinterpret_cast<const float4*>(&q[((size_t)b * NN + n0 + n) * 64 + kq * 4]);
        Qs[n * 68 + kq * 4 + 0] = f2tf(f.x); Qs[n * 68 + kq * 4 + 1] = f2tf(f.y);
        Qs[n * 68 + kq * 4 + 2] = f2tf(f.z); Qs[n * 68 + kq * 4 + 3] = f2tf(f.w);
    }
    if (t < 192) dn[t] = disc[((size_t)b * NN + n0) * 3 + t];

    // ----- compute qb[a] = q @ lt[a]^T in-block (tf32 MMA) -----
    const float* lt_ptrs[3] = {xlt, ylt, zlt};
    int qrow0 = (warp & 3) * 16;
    int qcol0 = (warp >> 2) * 32;
    for (int a = 0; a < 3; a++) {
        __syncthreads();  // Qs ready (a=0) / previous axis MMA done reading Ks
        for (int i = t; i < 64 * 64; i += 256) {
            int r = i >> 6, kk = i & 63;
            float vlt = (r < 63) ? lt_ptrs[a][r * 64 + kk] : 0.f;
            Ks[r * 68 + kk] = f2tf(vlt);
        }
        __syncthreads();
        float c2[4][4] = {};
#pragma unroll
        for (int ks = 0; ks < 8; ks++) {
            unsigned af[4], bf[4][2];
            int col = ks * 8 + (lane & 3);
            af[0] = Qs[(qrow0 + (lane >> 2)) * 68 + col];
            af[1] = Qs[(qrow0 + 8 + (lane >> 2)) * 68 + col];
            af[2] = Qs[(qrow0 + (lane >> 2)) * 68 + col + 4];
            af[3] = Qs[(qrow0 + 8 + (lane >> 2)) * 68 + col + 4];
#pragma unroll
            for (int nt = 0; nt < 4; nt++) {
                int cm = qcol0 + nt * 8 + (lane >> 2);
                bf[nt][0] = Ks[cm * 68 + col];
                bf[nt][1] = Ks[cm * 68 + col + 4];
            }
#pragma unroll
            for (int nt = 0; nt < 4; nt++) mma_tf32(c2[nt], af, bf[nt]);
        }
#pragma unroll
        for (int nt = 0; nt < 4; nt++)
#pragma unroll
            for (int h = 0; h < 2; h++) {
                int row = qrow0 + h * 8 + (lane >> 2);
                int col = qcol0 + nt * 8 + (lane & 3) * 2;
                qb[a * 4096 + row * 64 + col]     = c2[nt][h * 2 + 0];
                qb[a * 4096 + row * 64 + col + 1] = c2[nt][h * 2 + 1];
            }
    }

    int dn_r[2][2][3];
#pragma unroll
    for (int mt = 0; mt < 2; mt++)
#pragma unroll
        for (int h = 0; h < 2; h++) {
            int row_l = wr * 32 + mt * 16 + h * 8 + (lane >> 2);
#pragma unroll
            for (int a = 0; a < 3; a++) dn_r[mt][h][a] = dn[row_l * 3 + a];
        }

    float rmx[2][2], rsm[2][2];
#pragma unroll
    for (int mt = 0; mt < 2; mt++)
#pragma unroll
        for (int h = 0; h < 2; h++) { rmx[mt][h] = -1e30f; rsm[mt][h] = 0.f; }

    for (int m0c = 0; m0c < NN; m0c += 128) {
        __syncthreads();
        // load K chunk (128 x 64) tf32
#pragma unroll
        for (int i = 0; i < 8; i++) {
            int idx = t + i * 256;
            int m = idx >> 4, kq = idx & 15;
            float4 f = *reinterpret_cast<const float4*>(
                &k[((size_t)b * NN + m0c + m) * 64 + kq * 4]);
            Ks[m * 68 + kq * 4 + 0] = f2tf(f.x); Ks[m * 68 + kq * 4 + 1] = f2tf(f.y);
            Ks[m * 68 + kq * 4 + 2] = f2tf(f.z); Ks[m * 68 + kq * 4 + 3] = f2tf(f.w);
        }
        dm[t] = disc[((size_t)b * NN + m0c) * 3 + t];
        if (t + 256 < 384) dm[t + 256] = disc[((size_t)b * NN + m0c) * 3 + t + 256];
        __syncthreads();

        float c[2][4][4] = {};
#pragma unroll
        for (int ks = 0; ks < 8; ks++) {
            unsigned af[2][4], bf[4][2];
            int col = ks * 8 + (lane & 3);
#pragma unroll
            for (int mt = 0; mt < 2; mt++) {
                int row = wr * 32 + mt * 16 + (lane >> 2);
                af[mt][0] = Qs[row * 68 + col];
                af[mt][1] = Qs[(row + 8) * 68 + col];
                af[mt][2] = Qs[row * 68 + col + 4];
                af[mt][3] = Qs[(row + 8) * 68 + col + 4];
            }
#pragma unroll
            for (int nt = 0; nt < 4; nt++) {
                int cm = wc * 32 + nt * 8 + (lane >> 2);
                bf[nt][0] = Ks[cm * 68 + col];
                bf[nt][1] = Ks[cm * 68 + col + 4];
            }
#pragma unroll
            for (int mt = 0; mt < 2; mt++)
#pragma unroll
                for (int nt = 0; nt < 4; nt++) mma_tf32(c[mt][nt], af[mt], bf[nt]);
        }

        // bias + stats + store raw energy
#pragma unroll
        for (int mt = 0; mt < 2; mt++)
#pragma unroll
            for (int h = 0; h < 2; h++) {
                int row_l = wr * 32 + mt * 16 + h * 8 + (lane >> 2);
                float ev[4][2];
#pragma unroll
                for (int nt = 0; nt < 4; nt++) {
                    int col0 = wc * 32 + nt * 8 + (lane & 3) * 2;
#pragma unroll
                    for (int j = 0; j < 2; j++) {
                        int col = col0 + j;
                        float e = c[mt][nt][h * 2 + j];
#pragma unroll
                        for (int a = 0; a < 3; a++) {
                            int idx = dm[col * 3 + a] - dn_r[mt][h][a] + (BINS - 1);
                            e += qb[a * 4096 + row_l * 64 + idx];
                        }
                        ev[nt][j] = e;
                    }
                }
                float tm = ev[0][0];
#pragma unroll
                for (int nt = 0; nt < 4; nt++)
#pragma unroll
                    for (int j = 0; j < 2; j++) tm = fmaxf(tm, ev[nt][j]);
                float ts = 0.f;
#pragma unroll
                for (int nt = 0; nt < 4; nt++)
#pragma unroll
                    for (int j = 0; j < 2; j++) ts += __expf(ev[nt][j] - tm);
                float nm = fmaxf(rmx[mt][h], tm);
                rsm[mt][h] = rsm[mt][h] * __expf(rmx[mt][h] - nm) + ts * __expf(tm - nm);
                rmx[mt][h] = nm;
#pragma unroll
                for (int nt = 0; nt < 4; nt++) {
                    int col0 = wc * 32 + nt * 8 + (lane & 3) * 2;
                    float2 st = make_float2(ev[nt][0], ev[nt][1]);
                    *reinterpret_cast<float2*>(
                        &energy[((size_t)b * NN + n0 + row_l) * NN + m0c + col0]) = st;
                }
            }
    }

    // quad reduce + cross-warp (wc) merge
#pragma unroll
    for (int mt = 0; mt < 2; mt++)
#pragma unroll
        for (int h = 0; h < 2; h++) {
            float tm = rmx[mt][h], ts = rsm[mt][h];
#pragma unroll
            for (int d = 1; d < 4; d <<= 1) {
                float om = __shfl_xor_sync(0xffffffffu, tm, d);
                float os = __shfl_xor_sync(0xffffffffu, ts, d);
                float nm = fmaxf(tm, om);
                ts = ts * __expf(tm - nm) + os * __expf(om - nm);
                tm = nm;
            }
            if ((lane & 3) == 0) {
                int row_l = wr * 32 + mt * 16 + h * 8 + (lane >> 2);
                red[(wc * 64 + row_l) * 2 + 0] = tm;
                red[(wc * 64 + row_l) * 2 + 1] = ts;
            }
        }
    __syncthreads();
    if (t < 64) {
        float m = -1e30f, s = 0.f;
#pragma unroll
        for (int w = 0; w < 4; w++) {
            float mw = red[(w * 64 + t) * 2 + 0];
            float sw = red[(w * 64 + t) * 2 + 1];
            float nm = fmaxf(m, mw);
            s = s * __expf(m - nm) + sw * __expf(mw - nm);
            m = nm;
        }
        rowmax[b * NN + n0 + t]    = m;
        rowsuminv[b * NN + n0 + t] = 1.f / s;
    }
}

// ---------------- K5: xd = x - (V @ softmax(E)) * colscale, fully fused --------------
// Reads RAW energy; applies p = exp(e-rowmax)*rowsuminv inline; accumulates colsum
// in-block (k loop covers ALL n, so block-local colsum is the global one).
__global__ void xr_tf32_kernel(const float* __restrict__ v, const float* __restrict__ energy,
                               const float* __restrict__ rowmax, const float* __restrict__ rowsuminv,
                               const float* __restrict__ x, float* __restrict__ xd)
{
    __shared__ unsigned As[128][36];  // [d][k]
    __shared__ unsigned Bs[32][136];  // [k][m]
    __shared__ float csr[256][4];
    __shared__ float cscale[128];
    int b  = blockIdx.z;
    int m0 = blockIdx.x * 128;
    int d0 = blockIdx.y * 128;
    int t  = threadIdx.x;
    int warp = t >> 5, lane = t & 31;
    int wm = warp >> 2, wn = warp & 3;
    float c[4][4][4] = {};
    float csum[4] = {0.f, 0.f, 0.f, 0.f};
    const float* vb = v + (size_t)b * CC * NN;
    const float* eb = energy + (size_t)b * NN * NN;
    const float* rm = rowmax + b * NN;
    const float* ri = rowsuminv + b * NN;

    for (int k0 = 0; k0 < NN; k0 += 32) {
#pragma unroll
        for (int i = 0; i < 4; i++) {
            int idx = t + i * 256;
            int dd = idx >> 3, kq = idx & 7;
            float4 f = *reinterpret_cast<const float4*>(&vb[(size_t)(d0 + dd) * NN + k0 + kq * 4]);
            As[dd][kq * 4 + 0] = f2tf(f.x); As[dd][kq * 4 + 1] = f2tf(f.y);
            As[dd][kq * 4 + 2] = f2tf(f.z); As[dd][kq * 4 + 3] = f2tf(f.w);
        }
#pragma unroll
        for (int i = 0; i < 4; i++) {
            int idx = t + i * 256;
            int kk = idx >> 5, mq = idx & 31;
            float4 f = *reinterpret_cast<const float4*>(&eb[(size_t)(k0 + kk) * NN + m0 + mq * 4]);
            float rmv = rm[k0 + kk], riv = ri[k0 + kk];
            float p0 = __expf(f.x - rmv) * riv;
            float p1 = __expf(f.y - rmv) * riv;
            float p2 = __expf(f.z - rmv) * riv;
            float p3 = __expf(f.w - rmv) * riv;
            csum[0] += p0; csum[1] += p1; csum[2] += p2; csum[3] += p3;
            Bs[kk][mq * 4 + 0] = f2tf(p0); Bs[kk][mq * 4 + 1] = f2tf(p1);
            Bs[kk][mq * 4 + 2] = f2tf(p2); Bs[kk][mq * 4 + 3] = f2tf(p3);
        }
        __syncthreads();
#pragma unroll
        for (int ks = 0; ks < 4; ks++) {
            unsigned af[4][4], bf[4][2];
#pragma unroll
            for (int mt = 0; mt < 4; mt++) {
                int row = wm * 64 + mt * 16 + (lane >> 2);
                int col = ks * 8 + (lane & 3);
                af[mt][0] = As[row][col];
                af[mt][1] = As[row + 8][col];
                af[mt][2] = As[row][col + 4];
                af[mt][3] = As[row + 8][col + 4];
            }
#pragma unroll
            for (int nt = 0; nt < 4; nt++) {
                int kk = ks * 8 + (lane & 3);
                int cm = wn * 32 + nt * 8 + (lane >> 2);
                bf[nt][0] = Bs[kk][cm];
                bf[nt][1] = Bs[kk + 4][cm];
            }
#pragma unroll
            for (int mt = 0; mt < 4; mt++)
#pragma unroll
                for (int nt = 0; nt < 4; nt++) mma_tf32(c[mt][nt], af[mt], bf[nt]);
        }
        __syncthreads();
    }
    // block colsum reduce: thread t owned columns (t&31)*4 .. +3
#pragma unroll
    for (int cc2 = 0; cc2 < 4; cc2++) csr[t][cc2] = csum[cc2];
    __syncthreads();
    if (t < 128) {
        int g = t >> 2, lc = t & 3;
        float s = 0.f;
#pragma unroll
        for (int w = 0; w < 8; w++) s += csr[w * 32 + g][lc];
        cscale[t] = 1.f / (1e-9f + s);
    }
    __syncthreads();

#pragma unroll
    for (int mt = 0; mt < 4; mt++)
#pragma unroll
        for (int h = 0; h < 2; h++) {
            int dd = d0 + wm * 64 + mt * 16 + h * 8 + (lane >> 2);
#pragma unroll
            for (int nt = 0; nt < 4; nt++) {
                int mloc = wn * 32 + nt * 8 + (lane & 3) * 2;
                float s0 = cscale[mloc], s1 = cscale[mloc + 1];
                size_t idx = ((size_t)b * CC + dd) * NN + m0 + mloc;
                float2 xv = *reinterpret_cast<const float2*>(&x[idx]);
                float2 o;
                o.x = xv.x - c[mt][nt][h * 2 + 0] * s0;
                o.y = xv.y - c[mt][nt][h * 2 + 1] * s1;
                *reinterpret_cast<float2*>(&xd[idx]) = o;
            }
        }
}

// ---------------- K6: out = x + relu(BN(Wt @ xd + bt))  (tf32 MMA) -------------------
__global__ void final_tf32_kernel(const float* __restrict__ Wt, const float* __restrict__ xdin,
                                  const float* __restrict__ bt, const float* __restrict__ gamma,
                                  const float* __restrict__ beta, const float* __restrict__ mean,
                                  const float* __restrict__ var, const float* __restrict__ x,
                                  float* __restrict__ out)
{
    __shared__ unsigned As[128][36];
    __shared__ unsigned Bs[32][136];
    int b  = blockIdx.z;
    int m0 = blockIdx.x * 128;
    int o0 = blockIdx.y * 128;
    int t  = threadIdx.x;
    int warp = t >> 5, lane = t & 31;
    int wm = warp >> 2, wn = warp & 3;
    float c[4][4][4] = {};
    const float* xb = xdin + (size_t)b * CC * NN;

    for (int k0 = 0; k0 < CC; k0 += 32) {
#pragma unroll
        for (int i = 0; i < 4; i++) {
            int idx = t + i * 256;
            int dd = idx >> 3, kq = idx & 7;
            float4 f = *reinterpret_cast<const float4*>(&Wt[(o0 + dd) * CC + k0 + kq * 4]);
            As[dd][kq * 4 + 0] = f2tf(f.x); As[dd][kq * 4 + 1] = f2tf(f.y);
            As[dd][kq * 4 + 2] = f2tf(f.z); As[dd][kq * 4 + 3] = f2tf(f.w);
        }
#pragma unroll
        for (int i = 0; i < 4; i++) {
            int idx = t + i * 256;
            int kk = idx >> 5, mq = idx & 31;
            float4 f = *reinterpret_cast<const float4*>(&xb[(size_t)(k0 + kk) * NN + m0 + mq * 4]);
            Bs[kk][mq * 4 + 0] = f2tf(f.x); Bs[kk][mq * 4 + 1] = f2tf(f.y);
            Bs[kk][mq * 4 + 2] = f2tf(f.z); Bs[kk][mq * 4 + 3] = f2tf(f.w);
        }
        __syncthreads();
#pragma unroll
        for (int ks = 0; ks < 4; ks++) {
            unsigned af[4][4], bf[4][2];
#pragma unroll
            for (int mt = 0; mt < 4; mt++) {
                int row = wm * 64 + mt * 16 + (lane >> 2);
                int col = ks * 8 + (lane & 3);
                af[mt][0] = As[row][col];
                af[mt][1] = As[row + 8][col];
                af[mt][2] = As[row][col + 4];
                af[mt][3] = As[row + 8][col + 4];
            }
#pragma unroll
            for (int nt = 0; nt < 4; nt++) {
                int kk = ks * 8 + (lane & 3);
                int cm = wn * 32 + nt * 8 + (lane >> 2);
                bf[nt][0] = Bs[kk][cm];
                bf[nt][1] = Bs[kk + 4][cm];
            }
#pragma unroll
            for (int mt = 0; mt < 4; mt++)
#pragma unroll
                for (int nt = 0; nt < 4; nt++) mma_tf32(c[mt][nt], af[mt], bf[nt]);
        }
        __syncthreads();
    }
#pragma unroll
    for (int mt = 0; mt < 4; mt++)
#pragma unroll
        for (int h = 0; h < 2; h++) {
            int o = o0 + wm * 64 + mt * 16 + h * 8 + (lane >> 2);
            float inv = gamma[o] * rsqrtf(var[o] + 1e-5f);
            float mb = mean[o], beta_ = beta[o], btv = bt[o];
#pragma unroll
            for (int nt = 0; nt < 4; nt++) {
                int mm = m0 + wn * 32 + nt * 8 + (lane & 3) * 2;
                size_t idx = ((size_t)b * CC + o) * NN + mm;
                float2 xv = *reinterpret_cast<const float2*>(&x[idx]);
                float y0 = (c[mt][nt][h * 2 + 0] + btv - mb) * inv + beta_;
                float y1 = (c[mt][nt][h * 2 + 1] + btv - mb) * inv + beta_;
                float2 o2;
                o2.x = xv.x + fmaxf(y0, 0.f);
                o2.y = xv.y + fmaxf(y1, 0.f);
                *reinterpret_cast<float2*>(&out[idx]) = o2;
            }
        }
}

// -------------------------------- launcher -----------------------------------------
extern "C" void kernel_launch(void* const* d_in, const int* in_sizes, int n_in,
                              void* d_out, int out_size)
{
    const float* x    = (const float*)d_in[0];
    const int*   disc = (const int*)d_in[1];
    // d_in[2] = xyz (unused by the reference)
    const float* Wq   = (const float*)d_in[3];
    const float* Wk   = (const float*)d_in[4];
    const float* Wv   = (const float*)d_in[5];
    const float* bv   = (const float*)d_in[6];
    const float* xlt  = (const float*)d_in[7];
    const float* ylt  = (const float*)d_in[8];
    const float* zlt  = (const float*)d_in[9];
    const float* Wt   = (const float*)d_in[10];
    const float* bt   = (const float*)d_in[11];
    const float* gamma= (const float*)d_in[12];
    const float* beta = (const float*)d_in[13];
    const float* mean = (const float*)d_in[14];
    const float* var  = (const float*)d_in[15];
    float* out = (float*)d_out;

    float *q, *k, *v, *energy, *rowmax, *rowsuminv, *xd;
    cudaGetSymbolAddress((void**)&q, g_q);
    cudaGetSymbolAddress((void**)&k, g_k);
    cudaGetSymbolAddress((void**)&v, g_v);
    cudaGetSymbolAddress((void**)&energy, g_energy);
    cudaGetSymbolAddress((void**)&rowmax, g_rowmax);
    cudaGetSymbolAddress((void**)&rowsuminv, g_rowsuminv);
    cudaGetSymbolAddress((void**)&xd, g_xd);

    // dynamic smem for energy: Qs + Ks + qb + dn + dm + red
    const int smem_energy = (64 * 68 + 128 * 68) * 4 + 3 * 64 * 64 * 4
                          + 576 * 4 + 4 * 64 * 2 * 4;
    cudaFuncSetAttribute(energy_tf32_kernel, cudaFuncAttributeMaxDynamicSharedMemorySize, smem_energy);

    // K1: projections
    proj_kernel<true><<<dim3(NN / 64, 1, BB), 256>>>(Wq, x, nullptr, q, DQKD);
    proj_kernel<true><<<dim3(NN / 64, 1, BB), 256>>>(Wk, x, nullptr, k, DQKD);
    proj_kernel<false><<<dim3(NN / 64, CC / 64, BB), 256>>>(Wv, x, bv, v, CC);

    // K3: energy (+in-block qlt) + online row stats
    energy_tf32_kernel<<<dim3(NN / 64, BB), 256, smem_energy>>>(q, k, xlt, ylt, zlt, disc,
                                                                energy, rowmax, rowsuminv);

    // K5: fused softmax + colsum + xd = x - (V @ P) * colscale
    xr_tf32_kernel<<<dim3(NN / 128, CC / 128, BB), 256>>>(v, energy, rowmax, rowsuminv, x, xd);

    // K6: out = x + relu(BN(Wt @ xd + bt))
    final_tf32_kernel<<<dim3(NN / 128, CC / 128, BB), 256>>>(Wt, xd, bt, gamma, beta, mean, var, x, out);
}